// round 2
// baseline (speedup 1.0000x reference)
#include <cuda_runtime.h>
#include <math.h>
#include <stdint.h>

// Problem dims (fixed)
#define SEQ 256
#define BATCH 32
#define EDIM 256
#define HDIM 512
#define GDIM 2048           // 4*H
#define TTAGS 10
#define START_TAG 8
#define STOP_TAG 9
#define NEGV -10000.0f

#define NBLK 128            // recurrent persistent blocks (64 per direction)

// ---------------- scratch (static device globals; no runtime alloc) ----------
__device__ float g_xg[2u * SEQ * BATCH * GDIM];        // 128 MB: pre-activations (bias included)
__device__ float g_hseq[2u * SEQ * BATCH * HDIM];      // 32 MB: all hidden states
__device__ float g_hbuf[2 * 2 * BATCH * HDIM];         // [parity][dir][b][j]
__device__ float g_feats[SEQ * BATCH * TTAGS];         // emissions
__device__ int   g_sync;

// ---------------------------------------------------------------------------
// Kernel 1: xg[d][t][b][g] = sum_e emb[tok[b][t]][e] * w_ih_d[g][e] + b_d[g]
// Tiled fp32 GEMM, BM=128 (rows=(t,b)), BN=64, BK=16, 256 thr, 8x4 microtile.
// ---------------------------------------------------------------------------
__global__ void __launch_bounds__(256) xg_kernel(
    const int* __restrict__ tokens, const float* __restrict__ emb,
    const float* __restrict__ wf, const float* __restrict__ bf,
    const float* __restrict__ wb, const float* __restrict__ bb)
{
    const int bm = blockIdx.x;          // 64
    const int bn = blockIdx.y;          // 32
    const int dir = blockIdx.z;         // 2
    const int tid = threadIdx.x;

    if (bm == 0 && bn == 0 && dir == 0 && tid == 0) g_sync = 0;  // reset for recur kernel

    const float* w    = dir ? wb : wf;
    const float* bias = dir ? bb : bf;

    __shared__ int   rowtok[128];
    __shared__ float As[16 * 132];   // [k][m], padded
    __shared__ float Bs[16 * 68];    // [k][n], padded

    if (tid < 128) {
        int mg = bm * 128 + tid;                 // m = t*32 + b
        rowtok[tid] = tokens[(mg & 31) * SEQ + (mg >> 5)];
    }
    __syncthreads();

    const int ty = tid >> 4;   // 0..15 -> 8 rows
    const int tx = tid & 15;   // 0..15 -> 4 cols

    float acc[32];
    #pragma unroll
    for (int i = 0; i < 32; i++) acc[i] = 0.f;

    for (int k0 = 0; k0 < EDIM; k0 += 16) {
        // load A tile: 512 float4, 2 per thread (gathered embedding rows)
        #pragma unroll
        for (int it = 0; it < 2; ++it) {
            int f4 = tid + it * 256;
            int m = f4 >> 2, kq = f4 & 3;
            float4 v = *(const float4*)(emb + (size_t)rowtok[m] * EDIM + k0 + kq * 4);
            As[(kq * 4 + 0) * 132 + m] = v.x;
            As[(kq * 4 + 1) * 132 + m] = v.y;
            As[(kq * 4 + 2) * 132 + m] = v.z;
            As[(kq * 4 + 3) * 132 + m] = v.w;
        }
        // load B tile: 256 float4, 1 per thread
        {
            int n = tid >> 2, kq = tid & 3;
            float4 v = *(const float4*)(w + (size_t)(bn * 64 + n) * EDIM + k0 + kq * 4);
            Bs[(kq * 4 + 0) * 68 + n] = v.x;
            Bs[(kq * 4 + 1) * 68 + n] = v.y;
            Bs[(kq * 4 + 2) * 68 + n] = v.z;
            Bs[(kq * 4 + 3) * 68 + n] = v.w;
        }
        __syncthreads();
        #pragma unroll
        for (int k = 0; k < 16; k++) {
            const float* Ar = As + k * 132 + ty * 8;
            const float* Br = Bs + k * 68 + tx * 4;
            float4 a0 = *(const float4*)Ar;
            float4 a1 = *(const float4*)(Ar + 4);
            float4 b4 = *(const float4*)Br;
            float av[8] = {a0.x, a0.y, a0.z, a0.w, a1.x, a1.y, a1.z, a1.w};
            float bv[4] = {b4.x, b4.y, b4.z, b4.w};
            #pragma unroll
            for (int i = 0; i < 8; i++)
                #pragma unroll
                for (int j = 0; j < 4; j++)
                    acc[i * 4 + j] = fmaf(av[i], bv[j], acc[i * 4 + j]);
        }
        __syncthreads();
    }

    float4 bvec = *(const float4*)(bias + bn * 64 + tx * 4);
    #pragma unroll
    for (int i = 0; i < 8; i++) {
        int mg = bm * 128 + ty * 8 + i;
        float4 o;
        o.x = acc[i * 4 + 0] + bvec.x;
        o.y = acc[i * 4 + 1] + bvec.y;
        o.z = acc[i * 4 + 2] + bvec.z;
        o.w = acc[i * 4 + 3] + bvec.w;
        *(float4*)(g_xg + (size_t)(dir * 8192 + mg) * GDIM + bn * 64 + tx * 4) = o;
    }
}

// ---------------------------------------------------------------------------
// Kernel 2: persistent bidirectional LSTM recurrence.
// 128 blocks x 256 thr. Block = (dir, 8 hidden units -> 32 gate rows).
// W_hh rows held in registers (per-thread 64-float k-slice).
// h broadcast through L2 (__ldcg), parity double-buffered, grid spin-sync.
// ---------------------------------------------------------------------------
__device__ __forceinline__ void gsync(int target)
{
    __threadfence();
    __syncthreads();
    if (threadIdx.x == 0) {
        atomicAdd(&g_sync, 1);
        while (((volatile int*)&g_sync)[0] < target) { }
        __threadfence();
    }
    __syncthreads();
}

__global__ void __launch_bounds__(256, 1) recur_kernel(
    const float* __restrict__ whhf, const float* __restrict__ whhb)
{
    const int dir   = blockIdx.x >> 6;
    const int chunk = blockIdx.x & 63;
    const int j0    = chunk * 8;            // 8 hidden units per block
    const int tid   = threadIdx.x;
    // GEMM role: (kc = k-chunk of 64, r = gate-row 0..31)
    const int kc = tid >> 5;
    const int r  = tid & 31;
    const int q  = r >> 3, ur = r & 7;
    const int grow = q * HDIM + j0 + ur;    // global gate row
    // reduce/update role: (u = hidden unit 0..7, bt = batch 0..31)
    const int u  = tid >> 5;
    const int bt = tid & 31;

    __shared__ float part[8 * 32 * 33];     // [kc][r][b] padded

    const float* whh = dir ? whhb : whhf;
    float4 w4[16];
    {
        const float4* wrow = (const float4*)(whh + (size_t)grow * HDIM + kc * 64);
        #pragma unroll
        for (int i = 0; i < 16; i++) w4[i] = wrow[i];
    }

    // zero h double-buffer cooperatively (65536 floats / 128 blocks)
    g_hbuf[blockIdx.x * 512 + tid]       = 0.f;
    g_hbuf[blockIdx.x * 512 + 256 + tid] = 0.f;
    gsync(NBLK);

    float c = 0.f;   // cell state owned by (dir, j0+u, bt)

    for (int step = 0; step < SEQ; ++step) {
        const int t = dir ? (SEQ - 1 - step) : step;

        // prefetch this step's pre-activations (consumed after GEMM)
        const float* xgp = g_xg + ((size_t)(dir * SEQ + t) * BATCH + bt) * GDIM;
        float x0 = __ldg(xgp + 0 * HDIM + j0 + u);
        float x1 = __ldg(xgp + 1 * HDIM + j0 + u);
        float x2 = __ldg(xgp + 2 * HDIM + j0 + u);
        float x3 = __ldg(xgp + 3 * HDIM + j0 + u);

        // GEMM: partial[b] = dot(W_hh[grow, kc*64:+64], h_prev[b, kc*64:+64])
        const int rp = (step + 1) & 1;
        const float* hrd = g_hbuf + (rp * 2 + dir) * (BATCH * HDIM) + kc * 64;
        #pragma unroll 2
        for (int b = 0; b < BATCH; ++b) {
            const float4* hp = (const float4*)(hrd + b * HDIM);
            float a0 = 0.f, a1 = 0.f, a2 = 0.f, a3 = 0.f;
            #pragma unroll
            for (int i = 0; i < 16; i++) {
                float4 h = __ldcg(hp + i);
                a0 = fmaf(w4[i].x, h.x, a0);
                a1 = fmaf(w4[i].y, h.y, a1);
                a2 = fmaf(w4[i].z, h.z, a2);
                a3 = fmaf(w4[i].w, h.w, a3);
            }
            part[(kc * 32 + r) * 33 + b] = (a0 + a1) + (a2 + a3);
        }
        __syncthreads();

        // reduce across kc + add xg, then LSTM cell update for (u, bt)
        float gi = x0, gf = x1, gg = x2, go = x3;
        #pragma unroll
        for (int k2 = 0; k2 < 8; k2++) {
            gi += part[(k2 * 32 +  0 + u) * 33 + bt];
            gf += part[(k2 * 32 +  8 + u) * 33 + bt];
            gg += part[(k2 * 32 + 16 + u) * 33 + bt];
            go += part[(k2 * 32 + 24 + u) * 33 + bt];
        }
        float ig = 1.f / (1.f + expf(-gi));
        float fg = 1.f / (1.f + expf(-gf));
        float og = 1.f / (1.f + expf(-go));
        float gt = tanhf(gg);
        c = fg * c + ig * gt;
        float h = og * tanhf(c);

        const int wp = step & 1;
        const int j = j0 + u;
        g_hbuf[(wp * 2 + dir) * (BATCH * HDIM) + bt * HDIM + j] = h;
        g_hseq[((size_t)(dir * SEQ + t) * BATCH + bt) * HDIM + j] = h;

        gsync(NBLK * (step + 2));
    }
}

// ---------------------------------------------------------------------------
// Kernel 3: feats[s][b][tag] = [h_f | h_b] . w_out[tag] + b_out[tag]
// 256 blocks (one per s), 8 warps, warp per (s,b).
// ---------------------------------------------------------------------------
__global__ void __launch_bounds__(256) feats_kernel(
    const float* __restrict__ w_out, const float* __restrict__ b_out)
{
    const int s = blockIdx.x;
    const int w = threadIdx.x >> 5;
    const int l = threadIdx.x & 31;

    for (int b = w; b < BATCH; b += 8) {
        const float* hf = g_hseq + ((size_t)(0 * SEQ + s) * BATCH + b) * HDIM;
        const float* hb = g_hseq + ((size_t)(1 * SEQ + s) * BATCH + b) * HDIM;
        float hv[32];
        #pragma unroll
        for (int i = 0; i < 16; i++) hv[i]      = hf[l + 32 * i];
        #pragma unroll
        for (int i = 0; i < 16; i++) hv[16 + i] = hb[l + 32 * i];
        for (int tag = 0; tag < TTAGS; tag++) {
            const float* wr = w_out + (size_t)tag * (2 * HDIM);
            float p = 0.f;
            #pragma unroll
            for (int i = 0; i < 16; i++) p = fmaf(hv[i],      wr[l + 32 * i],        p);
            #pragma unroll
            for (int i = 0; i < 16; i++) p = fmaf(hv[16 + i], wr[HDIM + l + 32 * i], p);
            #pragma unroll
            for (int o = 16; o; o >>= 1) p += __shfl_down_sync(0xffffffffu, p, o);
            if (l == 0) g_feats[(s * BATCH + b) * TTAGS + tag] = p + b_out[tag];
        }
    }
}

// ---------------------------------------------------------------------------
// Kernel 4: CRF forward. One block (1 warp) per batch element.
// ---------------------------------------------------------------------------
__global__ void __launch_bounds__(32) crf_kernel(
    const int* __restrict__ lengths, const float* __restrict__ trans,
    float* __restrict__ out)
{
    const int b = blockIdx.x;
    const int l = threadIdx.x;

    __shared__ float tr[TTAGS * TTAGS];
    __shared__ float fv[16];
    __shared__ float fb[SEQ * TTAGS];

    for (int i = l; i < TTAGS * TTAGS; i += 32) tr[i] = trans[i];
    for (int i = l; i < SEQ * TTAGS; i += 32) {
        int s = i / TTAGS, tag = i - s * TTAGS;
        fb[i] = g_feats[(s * BATCH + b) * TTAGS + tag];
    }
    if (l < 16) fv[l] = (l == START_TAG) ? 0.f : NEGV;
    __syncwarp();

    const int len = lengths[b];
    for (int s = 0; s < len; s++) {
        float nv = 0.f;
        if (l < TTAGS) {
            float vs[TTAGS];
            float mx = -1e30f;
            #pragma unroll
            for (int p = 0; p < TTAGS; p++) {
                float v = fv[p] + tr[l * TTAGS + p];
                vs[p] = v;
                mx = fmaxf(mx, v);
            }
            float ss = 0.f;
            #pragma unroll
            for (int p = 0; p < TTAGS; p++) ss += expf(vs[p] - mx);
            nv = mx + logf(ss) + fb[s * TTAGS + l];
        }
        __syncwarp();
        if (l < TTAGS) fv[l] = nv;
        __syncwarp();
    }

    float term = (l < TTAGS) ? (fv[l] + tr[STOP_TAG * TTAGS + l]) : -1e30f;
    float mx = term;
    #pragma unroll
    for (int o = 16; o; o >>= 1) mx = fmaxf(mx, __shfl_down_sync(0xffffffffu, mx, o));
    mx = __shfl_sync(0xffffffffu, mx, 0);
    float e = (l < TTAGS) ? expf(term - mx) : 0.f;
    #pragma unroll
    for (int o = 16; o; o >>= 1) e += __shfl_down_sync(0xffffffffu, e, o);
    if (l == 0) out[b] = (mx + logf(e)) / (float)len;
}

// ---------------------------------------------------------------------------
extern "C" void kernel_launch(void* const* d_in, const int* in_sizes, int n_in,
                              void* d_out, int out_size)
{
    const int*   tokens  = (const int*)  d_in[0];
    const int*   lengths = (const int*)  d_in[1];
    const float* emb     = (const float*)d_in[2];
    const float* w_ih_f  = (const float*)d_in[3];
    const float* w_hh_f  = (const float*)d_in[4];
    const float* b_f     = (const float*)d_in[5];
    const float* w_ih_b  = (const float*)d_in[6];
    const float* w_hh_b  = (const float*)d_in[7];
    const float* b_b     = (const float*)d_in[8];
    const float* w_out   = (const float*)d_in[9];
    const float* b_out   = (const float*)d_in[10];
    const float* trans   = (const float*)d_in[11];
    float* out = (float*)d_out;

    xg_kernel<<<dim3(64, 32, 2), 256>>>(tokens, emb, w_ih_f, b_f, w_ih_b, b_b);
    recur_kernel<<<NBLK, 256>>>(w_hh_f, w_hh_b);
    feats_kernel<<<SEQ, 256>>>(w_out, b_out);
    crf_kernel<<<BATCH, 32>>>(lengths, trans, out);
}

// round 3
// speedup vs baseline: 1.6550x; 1.6550x over previous
#include <cuda_runtime.h>
#include <math.h>
#include <stdint.h>

// Problem dims (fixed)
#define SEQ 256
#define BATCH 32
#define EDIM 256
#define HDIM 512
#define GDIM 2048           // 4*H
#define TTAGS 10
#define START_TAG 8
#define STOP_TAG 9
#define NEGV -10000.0f

#define NBLK 128            // recurrent persistent blocks (64 per direction)

// packed fp32x2 helpers (sm_103a native; ptxas never emits from C++)
#define FMA2(acc, a, b) asm("fma.rn.f32x2 %0, %1, %2, %3;" : "=l"(acc) : "l"(a), "l"(b), "l"(acc))
#define SPLAT2(d, s)    asm("mov.b64 %0, {%1, %1};" : "=l"(d) : "f"(s))
#define UNPK2(lo, hi, s) asm("mov.b64 {%0, %1}, %2;" : "=f"(lo), "=f"(hi) : "l"(s))

// ---------------- scratch (static device globals; no runtime alloc) ----------
__device__ float g_xg[2u * SEQ * BATCH * GDIM];        // 128 MB: pre-activations (bias included)
__device__ float g_hseq[2u * SEQ * BATCH * HDIM];      // 32 MB: all hidden states
__device__ float g_hbuf[2 * 2 * BATCH * HDIM];         // [parity][dir][b][j]
__device__ float g_feats[SEQ * BATCH * TTAGS];         // emissions
__device__ int   g_sync;

// ---------------------------------------------------------------------------
// Kernel 1: xg[d][t][b][g] = sum_e emb[tok[b][t]][e] * w_ih_d[g][e] + b_d[g]
// BM=128 (rows=(t,b)), BN=128, BK=16, 256 thr, 8x8 microtile with fp32x2 FMA.
// ---------------------------------------------------------------------------
__global__ void __launch_bounds__(256) xg_kernel(
    const int* __restrict__ tokens, const float* __restrict__ emb,
    const float* __restrict__ wf, const float* __restrict__ bf,
    const float* __restrict__ wb, const float* __restrict__ bb)
{
    const int bm = blockIdx.x;          // 64
    const int bn = blockIdx.y;          // 16
    const int dir = blockIdx.z;         // 2
    const int tid = threadIdx.x;

    if (bm == 0 && bn == 0 && dir == 0 && tid == 0) g_sync = 0;  // reset for recur kernel

    const float* w    = dir ? wb : wf;
    const float* bias = dir ? bb : bf;

    __shared__ int   rowtok[128];
    __shared__ float As[16 * 132];   // [k][m], padded
    __shared__ float Bs[16 * 132];   // [k][n], padded

    if (tid < 128) {
        int mg = bm * 128 + tid;                 // m = t*32 + b
        rowtok[tid] = tokens[(mg & 31) * SEQ + (mg >> 5)];
    }
    __syncthreads();

    const int ty = tid >> 4;   // 0..15 -> 8 rows
    const int tx = tid & 15;   // 0..15 -> 8 cols

    uint64_t acc[4][8];        // [m-pair][n], packed f32x2 along m
    #pragma unroll
    for (int i = 0; i < 4; i++)
        #pragma unroll
        for (int j = 0; j < 8; j++) acc[i][j] = 0ull;

    for (int k0 = 0; k0 < EDIM; k0 += 16) {
        // A tile: 512 float4, 2 per thread (gathered embedding rows)
        #pragma unroll
        for (int it = 0; it < 2; ++it) {
            int f4 = tid + it * 256;
            int m = f4 >> 2, kq = f4 & 3;
            float4 v = *(const float4*)(emb + (size_t)rowtok[m] * EDIM + k0 + kq * 4);
            As[(kq * 4 + 0) * 132 + m] = v.x;
            As[(kq * 4 + 1) * 132 + m] = v.y;
            As[(kq * 4 + 2) * 132 + m] = v.z;
            As[(kq * 4 + 3) * 132 + m] = v.w;
        }
        // B tile: 512 float4, 2 per thread
        #pragma unroll
        for (int it = 0; it < 2; ++it) {
            int f4 = tid + it * 256;
            int n = f4 >> 2, kq = f4 & 3;
            float4 v = *(const float4*)(w + (size_t)(bn * 128 + n) * EDIM + k0 + kq * 4);
            Bs[(kq * 4 + 0) * 132 + n] = v.x;
            Bs[(kq * 4 + 1) * 132 + n] = v.y;
            Bs[(kq * 4 + 2) * 132 + n] = v.z;
            Bs[(kq * 4 + 3) * 132 + n] = v.w;
        }
        __syncthreads();
        #pragma unroll
        for (int k = 0; k < 16; k++) {
            ulonglong2 a0 = *(const ulonglong2*)(As + k * 132 + ty * 8);
            ulonglong2 a1 = *(const ulonglong2*)(As + k * 132 + ty * 8 + 4);
            float4 b0 = *(const float4*)(Bs + k * 132 + tx * 8);
            float4 b1 = *(const float4*)(Bs + k * 132 + tx * 8 + 4);
            float bv[8] = {b0.x, b0.y, b0.z, b0.w, b1.x, b1.y, b1.z, b1.w};
            uint64_t a2[4] = {a0.x, a0.y, a1.x, a1.y};
            #pragma unroll
            for (int j = 0; j < 8; j++) {
                uint64_t bs; SPLAT2(bs, bv[j]);
                FMA2(acc[0][j], a2[0], bs);
                FMA2(acc[1][j], a2[1], bs);
                FMA2(acc[2][j], a2[2], bs);
                FMA2(acc[3][j], a2[3], bs);
            }
        }
        __syncthreads();
    }

    float bb8[8];
    #pragma unroll
    for (int j = 0; j < 8; j++) bb8[j] = bias[bn * 128 + tx * 8 + j];

    #pragma unroll
    for (int mp = 0; mp < 4; mp++) {
        float r0[8], r1[8];
        #pragma unroll
        for (int j = 0; j < 8; j++) {
            float lo, hi; UNPK2(lo, hi, acc[mp][j]);
            r0[j] = lo + bb8[j];
            r1[j] = hi + bb8[j];
        }
        int m0 = bm * 128 + ty * 8 + mp * 2;
        float* o0 = g_xg + (size_t)(dir * 8192 + m0) * GDIM + bn * 128 + tx * 8;
        float* o1 = o0 + GDIM;
        *(float4*)(o0)     = make_float4(r0[0], r0[1], r0[2], r0[3]);
        *(float4*)(o0 + 4) = make_float4(r0[4], r0[5], r0[6], r0[7]);
        *(float4*)(o1)     = make_float4(r1[0], r1[1], r1[2], r1[3]);
        *(float4*)(o1 + 4) = make_float4(r1[4], r1[5], r1[6], r1[7]);
    }
}

// ---------------------------------------------------------------------------
// Grid barrier: release arrive + acquire poll (CG-style)
// ---------------------------------------------------------------------------
__device__ __forceinline__ void gsync(int target)
{
    __syncthreads();
    if (threadIdx.x == 0) {
        asm volatile("red.release.gpu.global.add.s32 [%0], 1;" :: "l"(&g_sync) : "memory");
        int v;
        do {
            asm volatile("ld.acquire.gpu.global.s32 %0, [%1];" : "=r"(v) : "l"(&g_sync) : "memory");
        } while (v < target);
    }
    __syncthreads();
}

// ---------------------------------------------------------------------------
// Kernel 2: persistent bidirectional LSTM recurrence.
// 128 blocks x 256 thr. Block = (dir, 8 hidden units -> 32 gate rows).
// W_hh rows in registers (packed f32x2). h_prev staged to smem each step.
// ---------------------------------------------------------------------------
__global__ void __launch_bounds__(256, 1) recur_kernel(
    const float* __restrict__ whhf, const float* __restrict__ whhb)
{
    extern __shared__ float dsm[];
    float4* hs4 = (float4*)dsm;               // 32 * 129 float4 (padded rows)
    float*  part = dsm + 4128 * 4;            // 8*32*33 floats

    const int dir   = blockIdx.x >> 6;
    const int chunk = blockIdx.x & 63;
    const int j0    = chunk * 8;              // 8 hidden units per block
    const int tid   = threadIdx.x;
    // GEMM role: (kc = k-chunk of 64, r = gate-row 0..31)
    const int kc = tid >> 5;
    const int r  = tid & 31;
    const int q  = r >> 3, ur = r & 7;
    const int grow = q * HDIM + j0 + ur;      // global gate row
    // reduce/update role: (u = hidden unit 0..7, bt = batch 0..31)
    const int u  = tid >> 5;
    const int bt = tid & 31;

    const float* whh = dir ? whhb : whhf;
    uint64_t w2[32];                          // 64 floats as 32 f32x2 pairs
    {
        const uint64_t* wrow = (const uint64_t*)(whh + (size_t)grow * HDIM + kc * 64);
        #pragma unroll
        for (int i = 0; i < 32; i++) w2[i] = wrow[i];
    }

    // zero h double-buffer cooperatively (65536 floats / 128 blocks)
    g_hbuf[blockIdx.x * 512 + tid]       = 0.f;
    g_hbuf[blockIdx.x * 512 + 256 + tid] = 0.f;
    gsync(NBLK);

    float c = 0.f;   // cell state owned by (dir, j0+u, bt)

    for (int step = 0; step < SEQ; ++step) {
        const int t = dir ? (SEQ - 1 - step) : step;

        // prefetch this step's pre-activations (consumed after GEMM)
        const float* xgp = g_xg + ((size_t)(dir * SEQ + t) * BATCH + bt) * GDIM;
        float x0 = __ldg(xgp + 0 * HDIM + j0 + u);
        float x1 = __ldg(xgp + 1 * HDIM + j0 + u);
        float x2 = __ldg(xgp + 2 * HDIM + j0 + u);
        float x3 = __ldg(xgp + 3 * HDIM + j0 + u);

        // stage h_prev[32][512] into smem (coalesced, MLP=16)
        const int rp = (step + 1) & 1;
        {
            const float4* hb4 = (const float4*)(g_hbuf + (rp * 2 + dir) * (BATCH * HDIM));
            #pragma unroll
            for (int it = 0; it < 16; ++it) {
                int f = tid + it * 256;            // 4096 float4 total
                int b = f >> 7, qq = f & 127;
                hs4[b * 129 + qq] = __ldcg(hb4 + f);
            }
        }
        __syncthreads();

        // GEMM: partial[b] = dot(W_hh[grow, kc*64:+64], h_prev[b, kc*64:+64])
        #pragma unroll 2
        for (int b = 0; b < BATCH; ++b) {
            const ulonglong2* hp = (const ulonglong2*)(hs4 + b * 129 + kc * 16);
            uint64_t a01 = 0ull, a23 = 0ull;
            #pragma unroll
            for (int i = 0; i < 16; i++) {
                ulonglong2 h = hp[i];
                FMA2(a01, w2[2 * i],     h.x);
                FMA2(a23, w2[2 * i + 1], h.y);
            }
            float s0, s1, s2, s3;
            UNPK2(s0, s1, a01);
            UNPK2(s2, s3, a23);
            part[(kc * 32 + r) * 33 + b] = (s0 + s1) + (s2 + s3);
        }
        __syncthreads();

        // reduce across kc + add xg, then LSTM cell update for (u, bt)
        float gi = x0, gf = x1, gg = x2, go = x3;
        #pragma unroll
        for (int k2 = 0; k2 < 8; k2++) {
            gi += part[(k2 * 32 +  0 + u) * 33 + bt];
            gf += part[(k2 * 32 +  8 + u) * 33 + bt];
            gg += part[(k2 * 32 + 16 + u) * 33 + bt];
            go += part[(k2 * 32 + 24 + u) * 33 + bt];
        }
        float ig = 1.f / (1.f + expf(-gi));
        float fg = 1.f / (1.f + expf(-gf));
        float og = 1.f / (1.f + expf(-go));
        float gt = tanhf(gg);
        c = fg * c + ig * gt;
        float h = og * tanhf(c);

        const int wp = step & 1;
        const int j = j0 + u;
        g_hbuf[(wp * 2 + dir) * (BATCH * HDIM) + bt * HDIM + j] = h;
        g_hseq[((size_t)(dir * SEQ + t) * BATCH + bt) * HDIM + j] = h;

        gsync(NBLK * (step + 2));
    }
}

// ---------------------------------------------------------------------------
// Kernel 3: feats[s][b][tag] = [h_f | h_b] . w_out[tag] + b_out[tag]
// ---------------------------------------------------------------------------
__global__ void __launch_bounds__(256) feats_kernel(
    const float* __restrict__ w_out, const float* __restrict__ b_out)
{
    const int s = blockIdx.x;
    const int w = threadIdx.x >> 5;
    const int l = threadIdx.x & 31;

    for (int b = w; b < BATCH; b += 8) {
        const float* hf = g_hseq + ((size_t)(0 * SEQ + s) * BATCH + b) * HDIM;
        const float* hb = g_hseq + ((size_t)(1 * SEQ + s) * BATCH + b) * HDIM;
        float hv[32];
        #pragma unroll
        for (int i = 0; i < 16; i++) hv[i]      = hf[l + 32 * i];
        #pragma unroll
        for (int i = 0; i < 16; i++) hv[16 + i] = hb[l + 32 * i];
        for (int tag = 0; tag < TTAGS; tag++) {
            const float* wr = w_out + (size_t)tag * (2 * HDIM);
            float p = 0.f;
            #pragma unroll
            for (int i = 0; i < 16; i++) p = fmaf(hv[i],      wr[l + 32 * i],        p);
            #pragma unroll
            for (int i = 0; i < 16; i++) p = fmaf(hv[16 + i], wr[HDIM + l + 32 * i], p);
            #pragma unroll
            for (int o = 16; o; o >>= 1) p += __shfl_down_sync(0xffffffffu, p, o);
            if (l == 0) g_feats[(s * BATCH + b) * TTAGS + tag] = p + b_out[tag];
        }
    }
}

// ---------------------------------------------------------------------------
// Kernel 4: CRF forward, factored logsumexp (1 exp + shfl gather per step).
// One warp per batch element.
// ---------------------------------------------------------------------------
__global__ void __launch_bounds__(32) crf_kernel(
    const int* __restrict__ lengths, const float* __restrict__ trans,
    float* __restrict__ out)
{
    const int b = blockIdx.x;
    const int l = threadIdx.x;

    __shared__ float fb[SEQ * TTAGS];
    for (int i = l; i < SEQ * TTAGS; i += 32) {
        int s = i / TTAGS, tg = i - s * TTAGS;
        fb[i] = g_feats[(s * BATCH + b) * TTAGS + tg];
    }

    float et[TTAGS];   // exp of transitions row for my "next" tag
    if (l < TTAGS) {
        #pragma unroll
        for (int p = 0; p < TTAGS; p++) et[p] = expf(trans[l * TTAGS + p]);
    }
    float fv = (l == START_TAG) ? 0.f : NEGV;
    __syncwarp();

    const int len = lengths[b];
    for (int s = 0; s < len; s++) {
        float v = (l < TTAGS) ? fv : -1e30f;
        #pragma unroll
        for (int o = 16; o; o >>= 1) v = fmaxf(v, __shfl_xor_sync(0xffffffffu, v, o));
        float e = (l < TTAGS) ? expf(fv - v) : 0.f;
        float sum = 0.f;
        #pragma unroll
        for (int p = 0; p < TTAGS; p++)
            sum = fmaf(__shfl_sync(0xffffffffu, e, p), et[p], sum);
        if (l < TTAGS) fv = v + logf(sum) + fb[s * TTAGS + l];
        __syncwarp();
    }

    float term = (l < TTAGS) ? (fv + trans[STOP_TAG * TTAGS + l]) : -1e30f;
    float mx = term;
    #pragma unroll
    for (int o = 16; o; o >>= 1) mx = fmaxf(mx, __shfl_xor_sync(0xffffffffu, mx, o));
    float e = (l < TTAGS) ? expf(term - mx) : 0.f;
    #pragma unroll
    for (int o = 16; o; o >>= 1) e += __shfl_xor_sync(0xffffffffu, e, o);
    if (l == 0) out[b] = (mx + logf(e)) / (float)len;
}

// ---------------------------------------------------------------------------
extern "C" void kernel_launch(void* const* d_in, const int* in_sizes, int n_in,
                              void* d_out, int out_size)
{
    const int*   tokens  = (const int*)  d_in[0];
    const int*   lengths = (const int*)  d_in[1];
    const float* emb     = (const float*)d_in[2];
    const float* w_ih_f  = (const float*)d_in[3];
    const float* w_hh_f  = (const float*)d_in[4];
    const float* b_f     = (const float*)d_in[5];
    const float* w_ih_b  = (const float*)d_in[6];
    const float* w_hh_b  = (const float*)d_in[7];
    const float* b_b     = (const float*)d_in[8];
    const float* w_out   = (const float*)d_in[9];
    const float* b_out   = (const float*)d_in[10];
    const float* trans   = (const float*)d_in[11];
    float* out = (float*)d_out;

    const int recur_smem = (32 * 129 * 4 + 8 * 32 * 33) * (int)sizeof(float);  // 99840 B
    cudaFuncSetAttribute(recur_kernel, cudaFuncAttributeMaxDynamicSharedMemorySize, recur_smem);

    xg_kernel<<<dim3(64, 16, 2), 256>>>(tokens, emb, w_ih_f, b_f, w_ih_b, b_b);
    recur_kernel<<<NBLK, 256, recur_smem>>>(w_hh_f, w_hh_b);
    feats_kernel<<<SEQ, 256>>>(w_out, b_out);
    crf_kernel<<<BATCH, 32>>>(lengths, trans, out);
}